// round 15
// baseline (speedup 1.0000x reference)
#include <cuda_runtime.h>
#include <cuda_fp16.h>
#include <cstdint>

// Problem constants
#define B_    8
#define IC_   16
#define H_    32
#define W_    32
#define OC_   32
#define TPO_  144               // tables per output channel
#define QTR_  36                // tables per warp (4-way split)
#define CHUNK_ 4                // fp16-accumulation chunk (36 = 9*4)

// Tiling
#define ROWS_PER_BLK 4
#define PW_   36                // padded width (cols 0..33 used; 34,35 pad)
#define CQ_   (3 * PW_)         // uint2 elems per channel (kh = 0..2)
#define TILEQ (IC_ * CQ_)       // 1728 uint2 = 13824 B

// packed f32x2 helpers
__device__ __forceinline__ unsigned long long pack_f32x2(float lo, float hi) {
    unsigned long long r;
    asm("mov.b64 %0, {%1, %2};" : "=l"(r)
        : "r"(__float_as_uint(lo)), "r"(__float_as_uint(hi)));
    return r;
}
__device__ __forceinline__ void add_f32x2(unsigned long long& acc, unsigned long long v) {
    asm("add.rn.f32x2 %0, %1, %2;" : "=l"(acc) : "l"(acc), "l"(v));
}
__device__ __forceinline__ float2 unpack_f32x2(unsigned long long v) {
    unsigned lo, hi;
    asm("mov.b64 {%0, %1}, %2;" : "=r"(lo), "=r"(hi) : "l"(v));
    return make_float2(__uint_as_float(lo), __uint_as_float(hi));
}

// ---------------------------------------------------------------------------
// Fused kernel. grid = (8 row-tiles, 16 oc-pairs, 8 batch) = 1024 blocks,
// 256 threads (8 warps). warp w -> oc = ogp*2 + (w&1), table quarter = w>>2.
// Per-table bilinear math in packed fp16 (HFMA2); per-table results
// accumulated in half2 for CHUNK_ tables, flushed to packed-fp32
// accumulators via add.rn.f32x2.
// ---------------------------------------------------------------------------
__global__ __launch_bounds__(256, 8)
void lut_conv_fused(const float* __restrict__ in,
                    const float* __restrict__ w_luts,
                    const int* __restrict__ mc,
                    const int* __restrict__ mkh,
                    const int* __restrict__ mkw,
                    float* __restrict__ out) {
    __shared__ uint2  s_q[TILEQ];               // 13824 B packed fp16 tile
    __shared__ uint4  s_rec[2 * TPO_ + 1];      //  4624 B (+1 zero pad rec)
    __shared__ float  s_a[2][TPO_];             //  1152 B constant terms
    __shared__ float  s_red[2][3][4][32];       //  3072 B partner accumulators

    const int tid = threadIdx.x;
    const int rt  = blockIdx.x;        // row tile 0..7
    const int ogp = blockIdx.y;        // oc pair 0..15
    const int b   = blockIdx.z;        // batch 0..7
    const int oh0 = rt * ROWS_PER_BLK;

    // ---- Phase 1a: stage tile. Threads 0..127: one (c, col-quad) each. ----
    if (tid < 128) {
        const int c = tid >> 3;
        const int q = tid & 7;               // float4 col group: iw = 4q..4q+3
        const float4* rowp = reinterpret_cast<const float4*>(
            in + ((size_t)b * IC_ + c) * H_ * W_) + q;
        float4 f[6];
        #pragma unroll
        for (int r = 0; r < 6; r++) {
            int ih = oh0 + r - 1;
            if ((unsigned)ih < (unsigned)H_) f[r] = rowp[ih * (W_ / 4)];
            else f[r] = make_float4(0.f, 0.f, 0.f, 0.f);
        }
        const float* ff = reinterpret_cast<const float*>(f);  // ff[r*4 + j]
        #pragma unroll
        for (int kh = 0; kh < 3; kh++) {
            #pragma unroll
            for (int j = 0; j < 4; j++) {
                __half2 lo = __floats2half2_rn(ff[kh * 4 + j],       ff[(kh + 1) * 4 + j]);
                __half2 hi = __floats2half2_rn(ff[(kh + 2) * 4 + j], ff[(kh + 3) * 4 + j]);
                uint2 v;
                v.x = *reinterpret_cast<unsigned*>(&lo);
                v.y = *reinterpret_cast<unsigned*>(&hi);
                s_q[(c * 3 + kh) * PW_ + 4 * q + 1 + j] = v;
            }
        }
    } else {
        // Threads 128..255: zero border columns pw=0 and pw=33.
        int t2 = tid - 128;
        if (t2 < 96) {
            int c   = t2 / 6;
            int rem = t2 - c * 6;
            int kh  = rem >> 1;
            int pw  = (rem & 1) ? 33 : 0;
            s_q[(c * 3 + kh) * PW_ + pw] = make_uint2(0u, 0u);
        }
    }

    // ---- Phase 1b: table records for this oc pair (288 of them) ----
    for (int j = tid; j < 2 * TPO_; j += 256) {
        int ocg = j / TPO_;
        int r   = j - ocg * TPO_;
        int t   = (ogp * 2 + ocg) * TPO_ + r;
        float4 w = __ldg(reinterpret_cast<const float4*>(w_luts) + t);
        float bb = 0.25f * (-w.x + w.y - w.z + w.w);
        float cc = 0.25f * (-w.x - w.y + w.z + w.w);
        float dd = 0.25f * ( w.x - w.y - w.z + w.w);
        s_a[ocg][r] = 0.25f * ((w.x + w.y) + (w.z + w.w));
        int m0 = 2 * t, m1 = 2 * t + 1;
        // byte offsets of uint2 element (c,kh,kw); lane adds lane*8
        unsigned off0 = (unsigned)(((mc[m0] * 3 + mkh[m0]) * PW_ + mkw[m0]) * 8);
        unsigned off1 = (unsigned)(((mc[m1] * 3 + mkh[m1]) * PW_ + mkw[m1]) * 8);
        __half2 b2 = __float2half2_rn(bb);
        __half2 c2 = __float2half2_rn(cc);
        __half2 d2 = __float2half2_rn(dd);
        uint4 rec;
        rec.x = *reinterpret_cast<unsigned*>(&b2);
        rec.y = *reinterpret_cast<unsigned*>(&c2);
        rec.z = *reinterpret_cast<unsigned*>(&d2);
        rec.w = off0 | (off1 << 16);
        s_rec[j] = rec;
    }
    if (tid == 0) s_rec[2 * TPO_] = make_uint4(0u, 0u, 0u, 0u);
    __syncthreads();

    // ---- Phase 2: main loop (36 iters per warp, 9 chunks of 4) ----
    const int lane = tid & 31;
    const int warp = tid >> 5;
    const int ocg  = warp & 1;         // oc within pair
    const int qtr  = warp >> 1;        // table quarter 0..3
    const int oc   = ogp * 2 + ocg;

    const uint4* __restrict__ recp = s_rec + ocg * TPO_ + qtr * QTR_;
    const char*  __restrict__ spb  = reinterpret_cast<const char*>(s_q) + lane * 8;

    unsigned long long accA = 0ull;    // packed fp32: rows 0,1
    unsigned long long accB = 0ull;    // packed fp32: rows 2,3

    // 2-stage software pipeline; final prefetch reads a valid pad record.
    uint4 rc = recp[0];
    uint2 q0 = *reinterpret_cast<const uint2*>(spb + (rc.w & 0xFFFFu));
    uint2 q1 = *reinterpret_cast<const uint2*>(spb + (rc.w >> 16));

    for (int ch = 0; ch < QTR_ / CHUNK_; ch++) {
        __half2 hacc_lo = __half2half2(__ushort_as_half(0));
        __half2 hacc_hi = __half2half2(__ushort_as_half(0));

        #pragma unroll
        for (int i = 0; i < CHUNK_; i++) {
            uint4 rcc = rc;
            uint2 a0  = q0;
            uint2 a1  = q1;
            rc = recp[ch * CHUNK_ + i + 1];
            q0 = *reinterpret_cast<const uint2*>(spb + (rc.w & 0xFFFFu));
            q1 = *reinterpret_cast<const uint2*>(spb + (rc.w >> 16));

            __half2 b2 = *reinterpret_cast<__half2*>(&rcc.x);
            __half2 c2 = *reinterpret_cast<__half2*>(&rcc.y);
            __half2 d2 = *reinterpret_cast<__half2*>(&rcc.z);
            __half2 x0lo = *reinterpret_cast<__half2*>(&a0.x);  // x0 rows 0,1
            __half2 x0hi = *reinterpret_cast<__half2*>(&a0.y);  // x0 rows 2,3
            __half2 x1lo = *reinterpret_cast<__half2*>(&a1.x);  // x1 rows 0,1
            __half2 x1hi = *reinterpret_cast<__half2*>(&a1.y);  // x1 rows 2,3

            // v = c*x1 + x0*(b + d*x1)   (3 fp16x2 ops per row-pair)
            __half2 tlo = __hfma2(d2, x1lo, b2);
            __half2 thi = __hfma2(d2, x1hi, b2);
            __half2 vlo = __hfma2(c2, x1lo, __hmul2(x0lo, tlo));
            __half2 vhi = __hfma2(c2, x1hi, __hmul2(x0hi, thi));

            hacc_lo = __hadd2(hacc_lo, vlo);
            hacc_hi = __hadd2(hacc_hi, vhi);
        }

        // flush chunk to packed fp32 accumulators
        float2 flo = __half22float2(hacc_lo);
        float2 fhi = __half22float2(hacc_hi);
        add_f32x2(accA, pack_f32x2(flo.x, flo.y));
        add_f32x2(accB, pack_f32x2(fhi.x, fhi.y));
    }

    float2 rA = unpack_f32x2(accA);
    float2 rB = unpack_f32x2(accB);
    float acc0 = rA.x, acc1 = rA.y, acc2 = rB.x, acc3 = rB.y;

    // ---- Phase 3: 4-way reduction + constant term, store ----
    if (qtr != 0) {
        s_red[ocg][qtr - 1][0][lane] = acc0;
        s_red[ocg][qtr - 1][1][lane] = acc1;
        s_red[ocg][qtr - 1][2][lane] = acc2;
        s_red[ocg][qtr - 1][3][lane] = acc3;
    }
    __syncthreads();
    if (qtr == 0) {
        // deterministic per-oc constant-term reduction (144 fp32 values)
        float s = 0.f;
        #pragma unroll
        for (int r = lane; r < TPO_; r += 32) s += s_a[ocg][r];
        #pragma unroll
        for (int o = 16; o >= 1; o >>= 1)
            s += __shfl_xor_sync(0xFFFFFFFFu, s, o);

        #pragma unroll
        for (int p = 0; p < 3; p++) {
            acc0 += s_red[ocg][p][0][lane];
            acc1 += s_red[ocg][p][1][lane];
            acc2 += s_red[ocg][p][2][lane];
            acc3 += s_red[ocg][p][3][lane];
        }
        acc0 += s; acc1 += s; acc2 += s; acc3 += s;

        float* ob = out + (((size_t)b * OC_ + oc) * H_ + oh0) * W_ + lane;
        ob[0]      = acc0;
        ob[W_]     = acc1;
        ob[2 * W_] = acc2;
        ob[3 * W_] = acc3;
    }
}

// ---------------------------------------------------------------------------
extern "C" void kernel_launch(void* const* d_in, const int* in_sizes, int n_in,
                              void* d_out, int out_size) {
    const float* input  = (const float*)d_in[0];   // (8,16,32,32)
    const float* w_luts = (const float*)d_in[1];   // (4608,4)
    const int*   mc     = (const int*)d_in[2];     // (9216,)
    const int*   mkh    = (const int*)d_in[3];     // (9216,)
    const int*   mkw    = (const int*)d_in[4];     // (9216,)
    float*       out    = (float*)d_out;           // (8,32,32,32)

    dim3 grid(H_ / ROWS_PER_BLK, OC_ / 2, B_);     // (8, 16, 8)
    lut_conv_fused<<<grid, 256>>>(input, w_luts, mc, mkh, mkw, out);
}